// round 11
// baseline (speedup 1.0000x reference)
#include <cuda_runtime.h>
#include <cuda_bf16.h>
#include <cstdint>

// VQ lookup via warp-level bf16 mma.sync (HMMA) + fused exact fp32 refinement.
//   dot(z,c) ~= zh*ch + zh*cl + zl*ch   (2-way bf16 Dekker split, 3 passes)
// R10: fully pipelined mainloop — cp.async prefetch (2 chunks ahead) of z fp32
// into smem staging + cb bf16 hi/lo; convert reads smem, never DRAM. 1 CTA/SM.

#define D_DIM   510
#define K_CODES 128
#define BM      128
#define KC      64           // K-chunk (elements)
#define NCH     8            // 8*64 = 512, cols 510/511 zeroed
#define TAU     0.01f
#define ST      144          // bf16 tile row stride BYTES (72 bf16)
#define ZSSTR   288          // z fp32 stage row stride BYTES (72 f32)

// smem byte offsets
#define SM_CSQ  0                        // 128 f32
#define SM_KF   512                      // 128 i32
#define SM_FLG  1024                     // 128 i32
#define SM_BV   1536                     // 2*128 f32
#define SM_SV   2560                     // 2*128 f32
#define SM_BK   3584                     // 2*128 i32
#define SM_ZT   4608                     // zh/zl tiles x2 bufs (4 x 18432)
#define SM_CB   78336                    // cbh/cbl tiles x2 bufs (4 x 18432)
#define SM_ZS   152064                   // z fp32 stage x2 bufs (2 x 36864)
#define BUFSZ   36864
#define SMEM_BYTES 225792

__device__ float g_csq[K_CODES];
__device__ __align__(128) __nv_bfloat16 g_cbh[K_CODES * 512];  // 512-padded rows
__device__ __align__(128) __nv_bfloat16 g_cbl[K_CODES * 512];

// ---------------------------------------------------------------- prep: c_sq + cb split
__global__ void prep_kernel(const float* __restrict__ cb) {
    int k = blockIdx.x, tid = threadIdx.x;
    float s = 0.f;
    for (int d = tid; d < 512; d += 256) {
        float v = (d < D_DIM) ? cb[k * D_DIM + d] : 0.f;
        __nv_bfloat16 h = __float2bfloat16(v);
        __nv_bfloat16 l = __float2bfloat16(v - __bfloat162float(h));
        g_cbh[k * 512 + d] = h;
        g_cbl[k * 512 + d] = l;
        s = fmaf(v, v, s);
    }
    #pragma unroll
    for (int off = 16; off; off >>= 1) s += __shfl_xor_sync(0xffffffffu, s, off);
    __shared__ float red[8];
    if ((tid & 31) == 0) red[tid >> 5] = s;
    __syncthreads();
    if (tid == 0) {
        float t = 0.f;
        #pragma unroll
        for (int i = 0; i < 8; i++) t += red[i];
        g_csq[k] = t;
    }
}

// ---------------------------------------------------------------- helpers
__device__ __forceinline__ void split2(float x, __nv_bfloat16& h, __nv_bfloat16& l) {
    h = __float2bfloat16(x);
    l = __float2bfloat16(x - __bfloat162float(h));
}
__device__ __forceinline__ uint32_t pack2(__nv_bfloat16 a, __nv_bfloat16 b) {
    return (uint32_t)__bfloat16_as_ushort(b) << 16 | (uint32_t)__bfloat16_as_ushort(a);
}
__device__ __forceinline__ void cp_async8(uint32_t dst, const void* src) {
    asm volatile("cp.async.ca.shared.global [%0], [%1], 8;" :: "r"(dst), "l"(src));
}
__device__ __forceinline__ void cp_async16(uint32_t dst, const void* src) {
    asm volatile("cp.async.ca.shared.global [%0], [%1], 16;" :: "r"(dst), "l"(src));
}
__device__ __forceinline__ void cp_commit() {
    asm volatile("cp.async.commit_group;");
}
template <int N>
__device__ __forceinline__ void cp_wait() {
    asm volatile("cp.async.wait_group %0;" :: "n"(N));
}
__device__ __forceinline__ void ldm4(uint32_t* r, uint32_t addr) {
    asm volatile("ldmatrix.sync.aligned.m8n8.x4.shared.b16 {%0,%1,%2,%3}, [%4];"
                 : "=r"(r[0]), "=r"(r[1]), "=r"(r[2]), "=r"(r[3]) : "r"(addr));
}
__device__ __forceinline__ void mma16816(float* d, const uint32_t* a,
                                         const uint32_t* b) {
    asm volatile(
        "mma.sync.aligned.m16n8k16.row.col.f32.bf16.bf16.f32 "
        "{%0,%1,%2,%3}, {%4,%5,%6,%7}, {%8,%9}, {%0,%1,%2,%3};"
        : "+f"(d[0]), "+f"(d[1]), "+f"(d[2]), "+f"(d[3])
        : "r"(a[0]), "r"(a[1]), "r"(a[2]), "r"(a[3]), "r"(b[0]), "r"(b[1]));
}
__device__ __forceinline__ void merge2(float& bv, float& sv, int& bk,
                                       float obv, float osv, int obk) {
    if (obv < bv) { sv = fminf(bv, osv); bv = obv; bk = obk; }
    else          { sv = fminf(sv, obv); }
}

extern __shared__ __align__(128) char smem[];

// ---------------------------------------------------------------- main kernel
__global__ __launch_bounds__(256, 1)
void vq_mma_kernel(const float* __restrict__ z,
                   const float* __restrict__ cb,
                   float* __restrict__ out) {
    const uint32_t sbase = (uint32_t)__cvta_generic_to_shared(smem);
    const int tid  = threadIdx.x;
    const int wid  = tid >> 5;
    const int lane = tid & 31;
    const int wr   = wid & 3;       // row group: 4 x 32 rows
    const int wc   = wid >> 2;      // code group: 2 x 64 codes
    const long long row0 = (long long)blockIdx.x * BM;

    if (tid < K_CODES) *(float*)(smem + SM_CSQ + tid * 4) = g_csq[tid];

    const float* zg = z + row0 * D_DIM;

    float acc[2][8][4];
    #pragma unroll
    for (int mt = 0; mt < 2; ++mt)
        #pragma unroll
        for (int nt = 0; nt < 8; ++nt)
            #pragma unroll
            for (int q = 0; q < 4; ++q) acc[mt][nt][q] = 0.f;

    // ldmatrix lane->address geometry (byte offsets within a tile)
    const uint32_t a_off = (uint32_t)((wr * 32 + (lane & 15)) * ST + ((lane >> 4) * 8) * 2);
    const uint32_t b_off = (uint32_t)((wc * 64 + ((lane >> 4) << 3) + (lane & 7)) * ST
                                      + (((lane >> 3) & 1) * 8) * 2);
    // convert geometry: 16 threads per row, 4 floats each
    const int lr0 = tid >> 4;
    const int lkq = (tid & 15) * 4;

    // -------- prefetch loader: z fp32 -> zstage[buf], cb hi/lo -> cb[buf]
    auto load_chunk = [&](int buf, int ch) {
        const uint32_t zs  = sbase + SM_ZS + (uint32_t)buf * BUFSZ;
        const uint32_t cbh = sbase + SM_CB + (uint32_t)buf * BUFSZ;
        const uint32_t cbl = cbh + 18432u;
        const bool tail = (ch == NCH - 1);
        #pragma unroll
        for (int it = 0; it < 16; ++it) {            // z: 128 rows x 32 f32-pairs
            const int r = it * 8 + wid;
            const uint32_t dst = zs + (uint32_t)(r * ZSSTR + lane * 8);
            if (tail && lane == 31) {
                asm volatile("st.shared.v2.f32 [%0], {%1,%2};"
                             :: "r"(dst), "f"(0.f), "f"(0.f));
            } else {
                cp_async8(dst, zg + (long long)r * D_DIM + ch * KC + lane * 2);
            }
        }
        #pragma unroll
        for (int it = 0; it < 4; ++it) {             // cb: 128 rows x 8 x 16B
            const int idx = it * 256 + tid;
            const int r = idx >> 3, q = idx & 7;
            const uint32_t doff = (uint32_t)(r * ST + q * 16);
            const char* sh = (const char*)g_cbh + ((long long)r * 512 + ch * KC) * 2 + q * 16;
            const char* sl = (const char*)g_cbl + ((long long)r * 512 + ch * KC) * 2 + q * 16;
            cp_async16(cbh + doff, sh);
            cp_async16(cbl + doff, sl);
        }
        cp_commit();
    };

    // -------- convert: zstage[buf] fp32 -> zh/zl bf16 tiles[buf]
    auto convert_chunk = [&](int buf) {
        const uint32_t zs  = sbase + SM_ZS + (uint32_t)buf * BUFSZ;
        const uint32_t zth = sbase + SM_ZT + (uint32_t)buf * BUFSZ;
        const uint32_t ztl = zth + 18432u;
        #pragma unroll
        for (int it = 0; it < 8; ++it) {
            const int r = lr0 + it * 16;
            float x0, x1, x2, x3;
            asm volatile("ld.shared.v4.f32 {%0,%1,%2,%3}, [%4];"
                         : "=f"(x0), "=f"(x1), "=f"(x2), "=f"(x3)
                         : "r"(zs + (uint32_t)(r * ZSSTR + lkq * 4)));
            __nv_bfloat16 h0,l0,h1,l1,h2,l2,h3,l3;
            split2(x0,h0,l0); split2(x1,h1,l1);
            split2(x2,h2,l2); split2(x3,h3,l3);
            const uint32_t so = (uint32_t)(r * ST + lkq * 2);
            asm volatile("st.shared.v2.b32 [%0], {%1,%2};"
                         :: "r"(zth + so), "r"(pack2(h0,h1)), "r"(pack2(h2,h3)));
            asm volatile("st.shared.v2.b32 [%0], {%1,%2};"
                         :: "r"(ztl + so), "r"(pack2(l0,l1)), "r"(pack2(l2,l3)));
        }
    };

    // -------- prologue: prefetch chunks 0 and 1, convert chunk 0
    load_chunk(0, 0);
    load_chunk(1, 1);
    cp_wait<1>();
    __syncthreads();
    convert_chunk(0);
    __syncthreads();

    // -------- pipelined mainloop
    for (int ch = 0; ch < NCH; ++ch) {
        const int buf  = ch & 1;
        const int nbuf = buf ^ 1;
        const uint32_t zth = sbase + SM_ZT + (uint32_t)buf * BUFSZ;
        const uint32_t ztl = zth + 18432u;
        const uint32_t cbh = sbase + SM_CB + (uint32_t)buf * BUFSZ;
        const uint32_t cbl = cbh + 18432u;

        #pragma unroll
        for (int ks = 0; ks < 4; ++ks) {
            const uint32_t kb = (uint32_t)(ks * 32);
            uint32_t ah[2][4], al[2][4];
            #pragma unroll
            for (int mt = 0; mt < 2; ++mt) {
                const uint32_t ao = a_off + (uint32_t)(mt * 16 * ST) + kb;
                ldm4(ah[mt], zth + ao);
                ldm4(al[mt], ztl + ao);
            }
            #pragma unroll
            for (int np = 0; np < 4; ++np) {
                const uint32_t bo = b_off + (uint32_t)(np * 16 * ST) + kb;
                uint32_t bh[4], bl[4];
                ldm4(bh, cbh + bo);
                ldm4(bl, cbl + bo);
                #pragma unroll
                for (int mt = 0; mt < 2; ++mt) {
                    mma16816(acc[mt][np*2+0], ah[mt], bh + 0);
                    mma16816(acc[mt][np*2+1], ah[mt], bh + 2);
                    mma16816(acc[mt][np*2+0], ah[mt], bl + 0);
                    mma16816(acc[mt][np*2+1], ah[mt], bl + 2);
                    mma16816(acc[mt][np*2+0], al[mt], bh + 0);
                    mma16816(acc[mt][np*2+1], al[mt], bh + 2);
                }
            }
        }

        if (ch + 1 < NCH) cp_wait<0>();
        __syncthreads();                 // MMA(ch) done everywhere; cp data visible
        if (ch + 2 < NCH) load_chunk(buf, ch + 2);
        if (ch + 1 < NCH) convert_chunk(nbuf);
        __syncthreads();                 // zt[nbuf] ready for next MMA
    }

    // ---- epilogue: top-2 per row
    const float* csq_s = (const float*)(smem + SM_CSQ);
    float* bvp = (float*)(smem + SM_BV);
    float* svp = (float*)(smem + SM_SV);
    int*   bkp = (int*)(smem + SM_BK);
    int*   flg = (int*)(smem + SM_FLG);

    #pragma unroll
    for (int mt = 0; mt < 2; ++mt) {
        #pragma unroll
        for (int rh = 0; rh < 2; ++rh) {
            float bv = 3.4e38f, sv = 3.4e38f;
            int bk = 0;
            #pragma unroll
            for (int nt = 0; nt < 8; ++nt) {
                #pragma unroll
                for (int s = 0; s < 2; ++s) {
                    const int c = wc * 64 + nt * 8 + (lane & 3) * 2 + s;
                    const float d2 = fmaf(-2.f, acc[mt][nt][rh * 2 + s], csq_s[c]);
                    if (d2 < bv) { sv = bv; bv = d2; bk = c; }
                    else if (d2 < sv) sv = d2;
                }
            }
            #pragma unroll
            for (int off = 1; off <= 2; off <<= 1) {
                float obv = __shfl_xor_sync(0xffffffffu, bv, off);
                float osv = __shfl_xor_sync(0xffffffffu, sv, off);
                int   obk = __shfl_xor_sync(0xffffffffu, bk, off);
                merge2(bv, sv, bk, obv, osv, obk);
            }
            if ((lane & 3) == 0) {
                const int r = wr * 32 + mt * 16 + rh * 8 + (lane >> 2);
                bvp[wc * 128 + r] = bv;
                svp[wc * 128 + r] = sv;
                bkp[wc * 128 + r] = bk;
            }
        }
    }
    __syncthreads();

    if (tid < BM) {
        float bv = bvp[tid], sv = svp[tid];
        int bk = bkp[tid];
        merge2(bv, sv, bk, bvp[128 + tid], svp[128 + tid], bkp[128 + tid]);
        *(int*)(smem + SM_KF + tid * 4) = bk;
        flg[tid] = ((sv - bv) < TAU) ? 1 : 0;
    }
    __syncthreads();

    // ---- gather: out[row] = codebook[kfin[row]]
    if (tid < 255) {
        const int dpos = tid * 2;
        float* ob = out + row0 * D_DIM + dpos;
        #pragma unroll 4
        for (int r = 0; r < BM; ++r) {
            int k = *(const int*)(smem + SM_KF + r * 4);
            float2 v = *(const float2*)(cb + k * D_DIM + dpos);
            *(float2*)(ob + (long long)r * D_DIM) = v;
        }
    }
    __syncthreads();

    // ---- fused exact refinement of near-tie rows (expected ~0.06 rows/CTA)
    for (int r = wid; r < BM; r += 8) {
        if (!flg[r]) continue;                      // warp-uniform branch
        const long long row = row0 + r;
        const float* zr = z + row * D_DIM;
        float zreg[16];
        #pragma unroll
        for (int t = 0; t < 16; ++t) {
            int d = lane + t * 32;
            zreg[t] = (d < D_DIM) ? zr[d] : 0.f;
        }
        float bv = 3.4e38f;
        int bk = 0;
        for (int c = 0; c < K_CODES; ++c) {
            const float* cr = cb + c * D_DIM;
            float s = 0.f;
            #pragma unroll
            for (int t = 0; t < 16; ++t) {
                int d = lane + t * 32;
                float cv = (d < D_DIM) ? cr[d] : 0.f;
                s = fmaf(zreg[t], cv, s);
            }
            #pragma unroll
            for (int off = 16; off; off >>= 1)
                s += __shfl_xor_sync(0xffffffffu, s, off);
            float d2 = fmaf(-2.f, s, csq_s[c]);
            if (d2 < bv) { bv = d2; bk = c; }       // strict <: lowest index wins ties
        }
        for (int d = lane; d < D_DIM; d += 32)
            out[row * D_DIM + d] = cb[bk * D_DIM + d];
    }
}

// ---------------------------------------------------------------- launch
extern "C" void kernel_launch(void* const* d_in, const int* in_sizes, int n_in,
                              void* d_out, int out_size) {
    const float* z  = (const float*)d_in[0];
    const float* cb = (const float*)d_in[1];
    float* out = (float*)d_out;

    cudaFuncSetAttribute(vq_mma_kernel, cudaFuncAttributeMaxDynamicSharedMemorySize,
                         SMEM_BYTES);

    const int n_rows  = in_sizes[0] / D_DIM;   // 131072
    const int nblocks = n_rows / BM;           // 1024

    prep_kernel<<<K_CODES, 256>>>(cb);
    vq_mma_kernel<<<nblocks, 256, SMEM_BYTES>>>(z, cb, out);
}

// round 12
// speedup vs baseline: 1.3975x; 1.3975x over previous
#include <cuda_runtime.h>
#include <cuda_bf16.h>
#include <cstdint>

// VQ lookup via warp-level bf16 mma.sync (HMMA) + fused exact fp32 refinement.
//   dot(z,c) ~= zh*ch + zh*cl + zl*ch   (2-way bf16 Dekker split, 3 passes)
// R11: R9 base (2 CTAs/SM) + minimal cp.async pipeline:
//   - single fp32 z staging buffer; z(ch+1) prefetched during MMA(ch)
//   - cb(ch) cp.async overlapped with the z convert phase
// smem = 113152 B -> still 2 CTAs/SM (the R10 lesson: never drop to 1).

#define D_DIM   510
#define K_CODES 128
#define BM      128
#define KC      64           // K-chunk (elements)
#define NCH     8            // 8*64 = 512, cols 510/511 zeroed
#define TAU     0.01f
#define ST      144          // bf16 tile row stride BYTES (72 bf16)
#define ZSSTR   272          // z fp32 stage row stride BYTES (68 f32)

// smem byte offsets
#define SM_CSQ  0                        // 128 f32
#define SM_KF   512                      // 128 i32
#define SM_FLG  1024                     // 128 i32
#define SM_BV   1536                     // 2*128 f32
#define SM_SV   2560                     // 2*128 f32
#define SM_BK   3584                     // 2*128 i32
#define SM_ZH   4608
#define SM_ZL   (SM_ZH + 128*ST)
#define SM_CH   (SM_ZL + 128*ST)
#define SM_CL   (SM_CH + 128*ST)
#define SM_ZS   (SM_CL + 128*ST)         // 78336: fp32 z stage, 128*272
#define SMEM_BYTES (SM_ZS + 128*ZSSTR)   // 113152

__device__ float g_csq[K_CODES];
__device__ __align__(128) __nv_bfloat16 g_cbh[K_CODES * 512];  // 512-padded rows
__device__ __align__(128) __nv_bfloat16 g_cbl[K_CODES * 512];

// ---------------------------------------------------------------- prep: c_sq + cb split
__global__ void prep_kernel(const float* __restrict__ cb) {
    int k = blockIdx.x, tid = threadIdx.x;
    float s = 0.f;
    for (int d = tid; d < 512; d += 256) {
        float v = (d < D_DIM) ? cb[k * D_DIM + d] : 0.f;
        __nv_bfloat16 h = __float2bfloat16(v);
        __nv_bfloat16 l = __float2bfloat16(v - __bfloat162float(h));
        g_cbh[k * 512 + d] = h;
        g_cbl[k * 512 + d] = l;
        s = fmaf(v, v, s);
    }
    #pragma unroll
    for (int off = 16; off; off >>= 1) s += __shfl_xor_sync(0xffffffffu, s, off);
    __shared__ float red[8];
    if ((tid & 31) == 0) red[tid >> 5] = s;
    __syncthreads();
    if (tid == 0) {
        float t = 0.f;
        #pragma unroll
        for (int i = 0; i < 8; i++) t += red[i];
        g_csq[k] = t;
    }
}

// ---------------------------------------------------------------- helpers
__device__ __forceinline__ void split2(float x, __nv_bfloat16& h, __nv_bfloat16& l) {
    h = __float2bfloat16(x);
    l = __float2bfloat16(x - __bfloat162float(h));
}
__device__ __forceinline__ uint32_t pack2(__nv_bfloat16 a, __nv_bfloat16 b) {
    return (uint32_t)__bfloat16_as_ushort(b) << 16 | (uint32_t)__bfloat16_as_ushort(a);
}
__device__ __forceinline__ void cp_async8(uint32_t dst, const void* src) {
    asm volatile("cp.async.ca.shared.global [%0], [%1], 8;" :: "r"(dst), "l"(src));
}
__device__ __forceinline__ void cp_async16(uint32_t dst, const void* src) {
    asm volatile("cp.async.ca.shared.global [%0], [%1], 16;" :: "r"(dst), "l"(src));
}
__device__ __forceinline__ void cp_commit() {
    asm volatile("cp.async.commit_group;");
}
template <int N>
__device__ __forceinline__ void cp_wait() {
    asm volatile("cp.async.wait_group %0;" :: "n"(N));
}
__device__ __forceinline__ void ldm4(uint32_t* r, uint32_t addr) {
    asm volatile("ldmatrix.sync.aligned.m8n8.x4.shared.b16 {%0,%1,%2,%3}, [%4];"
                 : "=r"(r[0]), "=r"(r[1]), "=r"(r[2]), "=r"(r[3]) : "r"(addr));
}
__device__ __forceinline__ void mma16816(float* d, const uint32_t* a,
                                         const uint32_t* b) {
    asm volatile(
        "mma.sync.aligned.m16n8k16.row.col.f32.bf16.bf16.f32 "
        "{%0,%1,%2,%3}, {%4,%5,%6,%7}, {%8,%9}, {%0,%1,%2,%3};"
        : "+f"(d[0]), "+f"(d[1]), "+f"(d[2]), "+f"(d[3])
        : "r"(a[0]), "r"(a[1]), "r"(a[2]), "r"(a[3]), "r"(b[0]), "r"(b[1]));
}
__device__ __forceinline__ void merge2(float& bv, float& sv, int& bk,
                                       float obv, float osv, int obk) {
    if (obv < bv) { sv = fminf(bv, osv); bv = obv; bk = obk; }
    else          { sv = fminf(sv, obv); }
}

extern __shared__ __align__(128) char smem[];

// ---------------------------------------------------------------- main kernel
__global__ __launch_bounds__(256, 2)
void vq_mma_kernel(const float* __restrict__ z,
                   const float* __restrict__ cb,
                   float* __restrict__ out) {
    const uint32_t sbase = (uint32_t)__cvta_generic_to_shared(smem);
    const int tid  = threadIdx.x;
    const int wid  = tid >> 5;
    const int lane = tid & 31;
    const int wr   = wid & 3;       // row group: 4 x 32 rows
    const int wc   = wid >> 2;      // code group: 2 x 64 codes
    const long long row0 = (long long)blockIdx.x * BM;

    if (tid < K_CODES) *(float*)(smem + SM_CSQ + tid * 4) = g_csq[tid];

    const float* zg = z + row0 * D_DIM;

    float acc[2][8][4];
    #pragma unroll
    for (int mt = 0; mt < 2; ++mt)
        #pragma unroll
        for (int nt = 0; nt < 8; ++nt)
            #pragma unroll
            for (int q = 0; q < 4; ++q) acc[mt][nt][q] = 0.f;

    // ldmatrix lane->address geometry (byte offsets within a tile)
    const uint32_t a_off = (uint32_t)((wr * 32 + (lane & 15)) * ST + ((lane >> 4) * 8) * 2);
    const uint32_t b_off = (uint32_t)((wc * 64 + ((lane >> 4) << 3) + (lane & 7)) * ST
                                      + (((lane >> 3) & 1) * 8) * 2);
    // convert geometry: 16 threads per row, 4 floats each
    const int lr0 = tid >> 4;
    const int lkq = (tid & 15) * 4;

    const uint32_t zs = sbase + SM_ZS;

    // -------- z stage prefetch (fp32 global -> smem stage), one chunk
    auto stage_z = [&](int ch) {
        const bool tail = (ch == NCH - 1);
        #pragma unroll
        for (int it = 0; it < 16; ++it) {            // 128 rows x 32 f32-pairs
            const int r = it * 8 + wid;
            const uint32_t dst = zs + (uint32_t)(r * ZSSTR + lane * 8);
            if (tail && lane == 31) {                // cols 510/511 -> zeros
                asm volatile("st.shared.v2.f32 [%0], {%1,%2};"
                             :: "r"(dst), "f"(0.f), "f"(0.f));
            } else {
                cp_async8(dst, zg + (long long)r * D_DIM + ch * KC + lane * 2);
            }
        }
        cp_commit();
    };

    // -------- cb tile prefetch (pre-split bf16 global -> smem tiles)
    auto stage_cb = [&](int ch) {
        #pragma unroll
        for (int it = 0; it < 4; ++it) {             // 128 rows x 8 x 16B
            const int idx = it * 256 + tid;
            const int r = idx >> 3, q = idx & 7;
            const uint32_t doff = (uint32_t)(r * ST + q * 16);
            const char* sh = (const char*)g_cbh + ((long long)r * 512 + ch * KC) * 2 + q * 16;
            const char* sl = (const char*)g_cbl + ((long long)r * 512 + ch * KC) * 2 + q * 16;
            cp_async16(sbase + SM_CH + doff, sh);
            cp_async16(sbase + SM_CL + doff, sl);
        }
        cp_commit();
    };

    // -------- convert: stage fp32 -> zh/zl bf16 tiles
    auto convert_z = [&]() {
        #pragma unroll
        for (int it = 0; it < 8; ++it) {
            const int r = lr0 + it * 16;
            float x0, x1, x2, x3;
            asm volatile("ld.shared.v4.f32 {%0,%1,%2,%3}, [%4];"
                         : "=f"(x0), "=f"(x1), "=f"(x2), "=f"(x3)
                         : "r"(zs + (uint32_t)(r * ZSSTR + lkq * 4)));
            __nv_bfloat16 h0,l0,h1,l1,h2,l2,h3,l3;
            split2(x0,h0,l0); split2(x1,h1,l1);
            split2(x2,h2,l2); split2(x3,h3,l3);
            const uint32_t so = (uint32_t)(r * ST + lkq * 2);
            asm volatile("st.shared.v2.b32 [%0], {%1,%2};"
                         :: "r"(sbase + SM_ZH + so), "r"(pack2(h0,h1)), "r"(pack2(h2,h3)));
            asm volatile("st.shared.v2.b32 [%0], {%1,%2};"
                         :: "r"(sbase + SM_ZL + so), "r"(pack2(l0,l1)), "r"(pack2(l2,l3)));
        }
    };

    // -------- prologue: stage z(0)
    stage_z(0);
    cp_wait<0>();
    __syncthreads();

    // -------- mainloop: cb(ch) under convert; z(ch+1) under MMA(ch)
    for (int ch = 0; ch < NCH; ++ch) {
        // zt/cb tiles are free here (prev MMA done); stage holds z(ch)
        stage_cb(ch);                    // group CB in flight
        convert_z();                     // compute overlaps CB
        __syncthreads();                 // all stage reads + zt writes done
        if (ch + 1 < NCH) {
            stage_z(ch + 1);             // group Z in flight (under MMA)
            cp_wait<1>();                // CB complete, Z may pend
        } else {
            cp_wait<0>();
        }
        __syncthreads();                 // cb tiles visible to all

        #pragma unroll
        for (int ks = 0; ks < 4; ++ks) {
            const uint32_t kb = (uint32_t)(ks * 32);
            uint32_t ah[2][4], al[2][4];
            #pragma unroll
            for (int mt = 0; mt < 2; ++mt) {
                const uint32_t ao = a_off + (uint32_t)(mt * 16 * ST) + kb;
                ldm4(ah[mt], sbase + SM_ZH + ao);
                ldm4(al[mt], sbase + SM_ZL + ao);
            }
            #pragma unroll
            for (int np = 0; np < 4; ++np) {
                const uint32_t bo = b_off + (uint32_t)(np * 16 * ST) + kb;
                uint32_t bh[4], bl[4];
                ldm4(bh, sbase + SM_CH + bo);
                ldm4(bl, sbase + SM_CL + bo);
                #pragma unroll
                for (int mt = 0; mt < 2; ++mt) {
                    mma16816(acc[mt][np*2+0], ah[mt], bh + 0);
                    mma16816(acc[mt][np*2+1], ah[mt], bh + 2);
                    mma16816(acc[mt][np*2+0], ah[mt], bl + 0);
                    mma16816(acc[mt][np*2+1], ah[mt], bl + 2);
                    mma16816(acc[mt][np*2+0], al[mt], bh + 0);
                    mma16816(acc[mt][np*2+1], al[mt], bh + 2);
                }
            }
        }

        cp_wait<0>();                    // z(ch+1) staged
        __syncthreads();                 // MMA done everywhere; tiles reusable
    }

    // ---- epilogue: top-2 per row
    const float* csq_s = (const float*)(smem + SM_CSQ);
    float* bvp = (float*)(smem + SM_BV);
    float* svp = (float*)(smem + SM_SV);
    int*   bkp = (int*)(smem + SM_BK);
    int*   flg = (int*)(smem + SM_FLG);

    #pragma unroll
    for (int mt = 0; mt < 2; ++mt) {
        #pragma unroll
        for (int rh = 0; rh < 2; ++rh) {
            float bv = 3.4e38f, sv = 3.4e38f;
            int bk = 0;
            #pragma unroll
            for (int nt = 0; nt < 8; ++nt) {
                #pragma unroll
                for (int s = 0; s < 2; ++s) {
                    const int c = wc * 64 + nt * 8 + (lane & 3) * 2 + s;
                    const float d2 = fmaf(-2.f, acc[mt][nt][rh * 2 + s], csq_s[c]);
                    if (d2 < bv) { sv = bv; bv = d2; bk = c; }
                    else if (d2 < sv) sv = d2;
                }
            }
            #pragma unroll
            for (int off = 1; off <= 2; off <<= 1) {
                float obv = __shfl_xor_sync(0xffffffffu, bv, off);
                float osv = __shfl_xor_sync(0xffffffffu, sv, off);
                int   obk = __shfl_xor_sync(0xffffffffu, bk, off);
                merge2(bv, sv, bk, obv, osv, obk);
            }
            if ((lane & 3) == 0) {
                const int r = wr * 32 + mt * 16 + rh * 8 + (lane >> 2);
                bvp[wc * 128 + r] = bv;
                svp[wc * 128 + r] = sv;
                bkp[wc * 128 + r] = bk;
            }
        }
    }
    __syncthreads();

    if (tid < BM) {
        float bv = bvp[tid], sv = svp[tid];
        int bk = bkp[tid];
        merge2(bv, sv, bk, bvp[128 + tid], svp[128 + tid], bkp[128 + tid]);
        *(int*)(smem + SM_KF + tid * 4) = bk;
        flg[tid] = ((sv - bv) < TAU) ? 1 : 0;
    }
    __syncthreads();

    // ---- gather: out[row] = codebook[kfin[row]]
    if (tid < 255) {
        const int dpos = tid * 2;
        float* ob = out + row0 * D_DIM + dpos;
        #pragma unroll 4
        for (int r = 0; r < BM; ++r) {
            int k = *(const int*)(smem + SM_KF + r * 4);
            float2 v = *(const float2*)(cb + k * D_DIM + dpos);
            *(float2*)(ob + (long long)r * D_DIM) = v;
        }
    }
    __syncthreads();

    // ---- fused exact refinement of near-tie rows (expected ~0.06 rows/CTA)
    for (int r = wid; r < BM; r += 8) {
        if (!flg[r]) continue;                      // warp-uniform branch
        const long long row = row0 + r;
        const float* zr = z + row * D_DIM;
        float zreg[16];
        #pragma unroll
        for (int t = 0; t < 16; ++t) {
            int d = lane + t * 32;
            zreg[t] = (d < D_DIM) ? zr[d] : 0.f;
        }
        float bv = 3.4e38f;
        int bk = 0;
        for (int c = 0; c < K_CODES; ++c) {
            const float* cr = cb + c * D_DIM;
            float s = 0.f;
            #pragma unroll
            for (int t = 0; t < 16; ++t) {
                int d = lane + t * 32;
                float cv = (d < D_DIM) ? cr[d] : 0.f;
                s = fmaf(zreg[t], cv, s);
            }
            #pragma unroll
            for (int off = 16; off; off >>= 1)
                s += __shfl_xor_sync(0xffffffffu, s, off);
            float d2 = fmaf(-2.f, s, csq_s[c]);
            if (d2 < bv) { bv = d2; bk = c; }       // strict <: lowest index wins ties
        }
        for (int d = lane; d < D_DIM; d += 32)
            out[row * D_DIM + d] = cb[bk * D_DIM + d];
    }
}

// ---------------------------------------------------------------- launch
extern "C" void kernel_launch(void* const* d_in, const int* in_sizes, int n_in,
                              void* d_out, int out_size) {
    const float* z  = (const float*)d_in[0];
    const float* cb = (const float*)d_in[1];
    float* out = (float*)d_out;

    cudaFuncSetAttribute(vq_mma_kernel, cudaFuncAttributeMaxDynamicSharedMemorySize,
                         SMEM_BYTES);

    const int n_rows  = in_sizes[0] / D_DIM;   // 131072
    const int nblocks = n_rows / BM;           // 1024

    prep_kernel<<<K_CODES, 256>>>(cb);
    vq_mma_kernel<<<nblocks, 256, SMEM_BYTES>>>(z, cb, out);
}